// round 1
// baseline (speedup 1.0000x reference)
#include <cuda_runtime.h>
#include <cuda_bf16.h>
#include <math.h>

// Problem constants (fixed shapes)
#define BB      16
#define HH      352
#define WW      1216
#define NN      (HH * WW)          // 428032
#define PP      100000
#define BN      (BB * NN)          // 6848512
#define TYPEIND 5
#define MAXD    40.0f

#define TILE    2048               // entries per scan block
#define BPB     (NN / TILE)        // 209 blocks per batch (exact)
#define NBLK    (BN / TILE)        // 3344 total scan blocks
#define WORDS   (BN / 32)          // 214016 selector words
#define WPB     (NN / 32)          // 13376 words per batch

// Static scratch (no allocations allowed)
__device__ unsigned d_selbits[WORDS];
__device__ int      d_blockSums[NBLK];
__device__ int      d_blockOffsets[NBLK];
__device__ int      d_valid[BB];
__device__ int      d_offset[BB];
__device__ int      d_compact[BN];

// ---------------------------------------------------------------------------
// Kernel 1: selector bits, pixel order. sel = (label==5) && (depth<40)
// ---------------------------------------------------------------------------
__global__ void k_selbits(const int* __restrict__ label,
                          const float* __restrict__ depth) {
    int gid = blockIdx.x * blockDim.x + threadIdx.x;   // < BN (exact multiple)
    bool sel = (label[gid] == TYPEIND) && (depth[gid] < MAXD);
    unsigned m = __ballot_sync(0xffffffffu, sel);
    if ((threadIdx.x & 31) == 0) d_selbits[gid >> 5] = m;
}

// helper: flag for permuted entry (b, j) given pj = perm[j]
__device__ __forceinline__ int sel_flag(const unsigned* sb, int pj) {
    return (sb[pj >> 5] >> (pj & 31)) & 1;
}

// ---------------------------------------------------------------------------
// Kernel 2: per-tile sums of permuted selector flags
// grid = NBLK, block = 256 threads x 8 items
// ---------------------------------------------------------------------------
__global__ void k_blocksums(const int* __restrict__ perm) {
    int blk = blockIdx.x;
    int b   = blk / BPB;
    int jb  = (blk - b * BPB) * TILE + threadIdx.x * 8;
    const unsigned* sb = d_selbits + b * WPB;

    int4 p0 = *reinterpret_cast<const int4*>(perm + jb);
    int4 p1 = *reinterpret_cast<const int4*>(perm + jb + 4);
    int pj[8] = {p0.x, p0.y, p0.z, p0.w, p1.x, p1.y, p1.z, p1.w};

    int cnt = 0;
#pragma unroll
    for (int k = 0; k < 8; k++) cnt += sel_flag(sb, pj[k]);

#pragma unroll
    for (int off = 16; off; off >>= 1)
        cnt += __shfl_down_sync(0xffffffffu, cnt, off);

    __shared__ int ws[8];
    if ((threadIdx.x & 31) == 0) ws[threadIdx.x >> 5] = cnt;
    __syncthreads();
    if (threadIdx.x == 0) {
        int s = 0;
#pragma unroll
        for (int w = 0; w < 8; w++) s += ws[w];
        d_blockSums[blk] = s;
    }
}

// ---------------------------------------------------------------------------
// Kernel 3: single-block exclusive scan of tile sums + batch stats
// 1 block x 1024 threads, 4 items each (4096 >= 3344)
// ---------------------------------------------------------------------------
__global__ void k_scan() {
    __shared__ int sSum[1024];
    __shared__ int sTot;
    int t = threadIdx.x;

    int v[4], s = 0;
#pragma unroll
    for (int k = 0; k < 4; k++) {
        int idx = t * 4 + k;
        v[k] = (idx < NBLK) ? d_blockSums[idx] : 0;
        s += v[k];
    }
    sSum[t] = s;
    __syncthreads();

    for (int off = 1; off < 1024; off <<= 1) {
        int add = (t >= off) ? sSum[t - off] : 0;
        __syncthreads();
        sSum[t] += add;
        __syncthreads();
    }
    int inclusive = sSum[t];
    if (t == 1023) sTot = inclusive;
    int run = inclusive - s;   // exclusive prefix for this thread's span
#pragma unroll
    for (int k = 0; k < 4; k++) {
        int idx = t * 4 + k;
        if (idx < NBLK) d_blockOffsets[idx] = run;
        run += v[k];
    }
    __syncthreads();
    if (t < BB) {
        int off_b = d_blockOffsets[t * BPB];
        int next  = (t == BB - 1) ? sTot : d_blockOffsets[(t + 1) * BPB];
        d_offset[t] = off_b;
        d_valid[t]  = next - off_b;
    }
}

// ---------------------------------------------------------------------------
// Kernel 4: order-preserving scatter into compact[]
// ---------------------------------------------------------------------------
__global__ void k_scatter(const int* __restrict__ perm) {
    int blk = blockIdx.x;
    int b   = blk / BPB;
    int jb  = (blk - b * BPB) * TILE + threadIdx.x * 8;
    const unsigned* sb = d_selbits + b * WPB;

    int4 p0 = *reinterpret_cast<const int4*>(perm + jb);
    int4 p1 = *reinterpret_cast<const int4*>(perm + jb + 4);
    int pj[8] = {p0.x, p0.y, p0.z, p0.w, p1.x, p1.y, p1.z, p1.w};

    int f[8], cnt = 0;
#pragma unroll
    for (int k = 0; k < 8; k++) { f[k] = sel_flag(sb, pj[k]); cnt += f[k]; }

    int lane = threadIdx.x & 31, wid = threadIdx.x >> 5;
    int inc = cnt;
#pragma unroll
    for (int off = 1; off < 32; off <<= 1) {
        int n = __shfl_up_sync(0xffffffffu, inc, off);
        if (lane >= off) inc += n;
    }
    __shared__ int ws[8];
    if (lane == 31) ws[wid] = inc;
    __syncthreads();
    int wbase = 0;
    for (int w = 0; w < wid; w++) wbase += ws[w];

    int base = d_blockOffsets[blk] + wbase + (inc - cnt);
    int bn = b * NN;
#pragma unroll
    for (int k = 0; k < 8; k++) {
        if (f[k]) d_compact[base++] = bn + pj[k];
    }
}

// ---------------------------------------------------------------------------
// Kernel 5: sample + back-project 3D points, write output + indicator
// out layout: pts [B,3,P] then indicator [B]
// ---------------------------------------------------------------------------
__global__ void k_output(const float* __restrict__ depth,
                         const float* __restrict__ invK,
                         const float* __restrict__ bind,
                         float* __restrict__ out) {
    int i = blockIdx.x * blockDim.x + threadIdx.x;
    if (i < BB)
        out[3 * BB * PP + i] = (d_valid[i] > 0) ? 1.0f : 0.0f;
    if (i >= BB * PP) return;

    int b = i / PP;
    int p = i - b * PP;
    int vn = d_valid[b];

    int idx = 0;
    if (vn > 0)
        idx = (int)fmodf(bind[i], (float)vn) + d_offset[b];

    int pos = d_compact[idx];          // global pixel index (b'*N + pix)
    int bb  = pos / NN;                // normally == b
    int pix = pos - bb * NN;

    float d = depth[pos];
    int   q = pix / WW;
    float y = (float)q;
    float x = (float)(pix - q * WW);
    float hx = x * d, hy = y * d;

    const float* M = invK + bb * 16;
#pragma unroll
    for (int c = 0; c < 3; c++) {
        float v = fmaf(M[c * 4 + 0], hx,
                  fmaf(M[c * 4 + 1], hy,
                  fmaf(M[c * 4 + 2], d, M[c * 4 + 3])));
        out[(b * 3 + c) * PP + p] = v;
    }
}

// ---------------------------------------------------------------------------
extern "C" void kernel_launch(void* const* d_in, const int* in_sizes, int n_in,
                              void* d_out, int out_size) {
    const float* predDepth  = (const float*)d_in[0];   // [B,1,H,W]
    const float* invcamK    = (const float*)d_in[1];   // [B,4,4]
    const int*   semLabel   = (const int*)  d_in[2];   // [B,1,H,W]
    const float* bind       = (const float*)d_in[3];   // [B,P]
    const int*   perm       = (const int*)  d_in[4];   // [N]
    float* out = (float*)d_out;

    k_selbits  <<<BN / 256, 256>>>(semLabel, predDepth);
    k_blocksums<<<NBLK, 256>>>(perm);
    k_scan     <<<1, 1024>>>();
    k_scatter  <<<NBLK, 256>>>(perm);
    k_output   <<<(BB * PP) / 256, 256>>>(predDepth, invcamK, bind, out);
}